// round 14
// baseline (speedup 1.0000x reference)
#include <cuda_runtime.h>
#include <cuda_fp16.h>
#include <cstdint>

#define BSZ   8
#define NSEQ  2048
#define EDIM  128
#define HEADS 4
#define DHEAD 32
#define NEGV  -1e9f
#define QS2    0.25503482120645087f          // (1/sqrt(32)) * log2(e)
#define EOFF   6.0f                          // fixed exponent offset (log2 domain)
#define NT     (NSEQ / 64)                   // 32 kv tiles

// Scratch. Q/K d-words and Vt kv-words are PERMUTED within 8-word groups
// (perm(x) = 2*(x&3) + (x>>2)) so mma B/A fragment pairs (t, t+4) are
// physically adjacent -> single LDS.64 / LDG.64.
__device__ unsigned g_qw[(size_t)BSZ * HEADS * NSEQ * (DHEAD / 2)];
__device__ unsigned g_kw[(size_t)BSZ * HEADS * NSEQ * (DHEAD / 2)];
__device__ __half   g_vt[(size_t)BSZ * HEADS * DHEAD * NSEQ];
__device__ float    g_attn[(size_t)BSZ * NSEQ * EDIM];
__device__ unsigned g_mask[(size_t)NSEQ * (NSEQ / 32)];

// --------------------------------------------------------------------------
__device__ __forceinline__ unsigned f2tf(float f) {
    unsigned r; asm("cvt.rna.tf32.f32 %0, %1;" : "=r"(r) : "f"(f)); return r;
}
__device__ __forceinline__ unsigned packh2(float a, float b) {
    __half2 h = __floats2half2_rn(a, b); return *(unsigned*)&h;
}
__device__ __forceinline__ unsigned cvt_h2(float a, float b) {
    unsigned r;
    asm("cvt.rn.f16x2.f32 %0, %1, %2;" : "=r"(r) : "f"(b), "f"(a));
    return r;
}
__device__ __forceinline__ unsigned ex2_h2(unsigned x) {
    unsigned r;
    asm("ex2.approx.f16x2 %0, %1;" : "=r"(r) : "r"(x));
    return r;
}
__device__ __forceinline__ void mma8(float* c,
                                     unsigned a0, unsigned a1, unsigned a2, unsigned a3,
                                     unsigned b0, unsigned b1) {
    asm volatile(
        "mma.sync.aligned.m16n8k8.row.col.f32.tf32.tf32.f32 "
        "{%0,%1,%2,%3}, {%4,%5,%6,%7}, {%8,%9}, {%0,%1,%2,%3};"
        : "+f"(c[0]), "+f"(c[1]), "+f"(c[2]), "+f"(c[3])
        : "r"(a0), "r"(a1), "r"(a2), "r"(a3), "r"(b0), "r"(b1));
}
__device__ __forceinline__ void mma16(float* c,
                                      unsigned a0, unsigned a1, unsigned a2, unsigned a3,
                                      unsigned b0, unsigned b1) {
    asm volatile(
        "mma.sync.aligned.m16n8k16.row.col.f32.f16.f16.f32 "
        "{%0,%1,%2,%3}, {%4,%5,%6,%7}, {%8,%9}, {%0,%1,%2,%3};"
        : "+f"(c[0]), "+f"(c[1]), "+f"(c[2]), "+f"(c[3])
        : "r"(a0), "r"(a1), "r"(a2), "r"(a3), "r"(b0), "r"(b1));
}
__device__ __forceinline__ void cpa16(void* dst, const void* src) {
    unsigned d = (unsigned)__cvta_generic_to_shared(dst);
    asm volatile("cp.async.ca.shared.global [%0], [%1], 16;" :: "r"(d), "l"(src));
}
__device__ __forceinline__ int permw(int x) { return 2 * (x & 3) + (x >> 2); }

// --------------------------------------------------------------------------
// Kernel 0: bit-pack adj[0]
// --------------------------------------------------------------------------
__global__ __launch_bounds__(256) void maskpack_kernel(const int* __restrict__ adj) {
    int gid  = blockIdx.x * 256 + threadIdx.x;
    int w    = gid >> 5;
    int lane = gid & 31;
    int n    = w >> 6;
    int word = w & 63;
    int v = adj[(size_t)n * NSEQ + word * 32 + lane];
    unsigned m = __ballot_sync(0xffffffffu, v != 0);
    if (lane == 0) g_mask[w] = m;
}

// --------------------------------------------------------------------------
// Shared GEMM body: single-shot cp.async of full K=128 fp32 tiles, ONE
// wait + barrier, then an IN-PLACE tf32 rounding pass (cvt.rna — restores
// R12 numerics; raw truncation in R13 cost 5x error), one barrier, then
// all 128 mmas.  A: 128 x 128 @ pitch 132; B: 64 x 128 @ pitch 132.
// --------------------------------------------------------------------------
#define GP 132
#define GEMM_SMEM_BYTES ((128 * GP + 64 * GP) * 4)   // 101376 B

__device__ __forceinline__ void gemm_body(
    unsigned* Xs, unsigned* Ws,
    const float* __restrict__ a_src, const float* __restrict__ b_src,
    int m0, int c0, int tid, int wp, int g, int t, float acc[8][4])
{
    #pragma unroll
    for (int i = tid; i < 4096; i += 256) {
        int r = i >> 5, c4 = (i & 31) * 4;
        cpa16(&Xs[r * GP + c4], &a_src[(size_t)(m0 + r) * EDIM + c4]);
    }
    #pragma unroll
    for (int i = tid; i < 2048; i += 256) {
        int r = i >> 5, c4 = (i & 31) * 4;
        cpa16(&Ws[r * GP + c4], &b_src[(size_t)(c0 + r) * EDIM + c4]);
    }
    asm volatile("cp.async.commit_group;" ::: "memory");
    asm volatile("cp.async.wait_group 0;" ::: "memory");
    __syncthreads();

    // in-place tf32 rounding pass (vectorized 128b round trips)
    #pragma unroll
    for (int i = tid; i < 1024; i += 256) {
        int r = i >> 3, c4 = (i & 7) * 16;
        uint4* p = (uint4*)&Xs[r * GP + c4];
        #pragma unroll
        for (int v4 = 0; v4 < 4; v4++) {
            uint4 w4 = p[v4];
            p[v4] = make_uint4(f2tf(__uint_as_float(w4.x)),
                               f2tf(__uint_as_float(w4.y)),
                               f2tf(__uint_as_float(w4.z)),
                               f2tf(__uint_as_float(w4.w)));
        }
    }
    #pragma unroll
    for (int i = tid; i < 512; i += 256) {
        int r = i >> 3, c4 = (i & 7) * 16;
        uint4* p = (uint4*)&Ws[r * GP + c4];
        #pragma unroll
        for (int v4 = 0; v4 < 4; v4++) {
            uint4 w4 = p[v4];
            p[v4] = make_uint4(f2tf(__uint_as_float(w4.x)),
                               f2tf(__uint_as_float(w4.y)),
                               f2tf(__uint_as_float(w4.z)),
                               f2tf(__uint_as_float(w4.w)));
        }
    }
    __syncthreads();

    #pragma unroll
    for (int kc = 0; kc < 16; kc++) {
        const unsigned* xr = &Xs[(wp * 16 + g) * GP + kc * 8 + t];
        unsigned a0 = xr[0], a1 = xr[8 * GP], a2 = xr[4], a3 = xr[8 * GP + 4];
        #pragma unroll
        for (int nt = 0; nt < 8; nt++) {
            unsigned b0 = Ws[(nt * 8 + g) * GP + kc * 8 + t];
            unsigned b1 = Ws[(nt * 8 + g) * GP + kc * 8 + t + 4];
            mma8(acc[nt], a0, a1, a2, a3, b0, b1);
        }
    }
}

// --------------------------------------------------------------------------
// Kernel 1: QKV projection, 256 thr, tile 128 x 64, single-shot smem load.
// --------------------------------------------------------------------------
__global__ __launch_bounds__(256) void qkv_proj_kernel(
    const float* __restrict__ x, const float* __restrict__ w,
    const float* __restrict__ bias)
{
    extern __shared__ unsigned dsm[];
    unsigned* Xs = dsm;
    unsigned* Ws = dsm + 128 * GP;

    const int tid = threadIdx.x;
    const int wp = tid >> 5, lane = tid & 31;
    const int g = lane >> 2, t = lane & 3;
    const int m0 = blockIdx.y * 128, c0 = blockIdx.x * 64;

    float acc[8][4];
    #pragma unroll
    for (int nt = 0; nt < 8; nt++)
        #pragma unroll
        for (int j = 0; j < 4; j++) acc[nt][j] = 0.f;

    gemm_body(Xs, Ws, x, w, m0, c0, tid, wp, g, t, acc);

    const int bb = m0 >> 11;
    const int n0 = m0 & (NSEQ - 1);
    const int mrow0 = m0 + wp * 16 + g;

    if (c0 < 256) {
        // ---- Q / K epilogue (permuted half2 words)
        #pragma unroll
        for (int nt = 0; nt < 8; nt++) {
            int cg = c0 + nt * 8 + 2 * t;
            float b0v = bias[cg], b1v = bias[cg + 1];
            int part = cg >> 7;
            int e = cg & 127, hh = e >> 5, d0 = e & 31;
            int wrd = d0 >> 1;
            int wperm = (wrd & ~7) | permw(wrd & 7);
            #pragma unroll
            for (int rr = 0; rr < 2; rr++) {
                int m = mrow0 + rr * 8;
                int bbm = m >> 11, n = m & (NSEQ - 1);
                int bh = bbm * HEADS + hh;
                float v0 = acc[nt][rr * 2 + 0] + b0v;
                float v1 = acc[nt][rr * 2 + 1] + b1v;
                if (part == 0) {
                    g_qw[((size_t)bh * NSEQ + n) * 16 + wperm] =
                        packh2(v0 * QS2, v1 * QS2);
                } else {
                    g_kw[((size_t)bh * NSEQ + n) * 16 + wperm] = packh2(v0, v1);
                }
            }
        }
    } else {
        // ---- V epilogue: stage [e][n] tile in smem, write coalesced
        __syncthreads();
        __half* sT = (__half*)Xs;   // 64 x 136 halves (fits in X region)
        #pragma unroll
        for (int nt = 0; nt < 8; nt++) {
            int cg = c0 + nt * 8 + 2 * t;
            float b0v = bias[cg], b1v = bias[cg + 1];
            int e0 = nt * 8 + 2 * t;
            #pragma unroll
            for (int rr = 0; rr < 2; rr++) {
                int nl = wp * 16 + g + rr * 8;
                sT[(e0)     * 136 + nl] = __float2half_rn(acc[nt][rr * 2 + 0] + b0v);
                sT[(e0 + 1) * 136 + nl] = __float2half_rn(acc[nt][rr * 2 + 1] + b1v);
            }
        }
        __syncthreads();

        const unsigned* sTw = (const unsigned*)sT;   // row stride 68 words
        const int ebase = c0 - 256;
        #pragma unroll
        for (int r8 = 0; r8 < 8; r8++) {
            int row = wp * 8 + r8;
            int e = ebase + row;
            int h = e >> 5, d0v = e & 31;
            size_t basev = ((size_t)(bb * HEADS + h) * DHEAD + d0v) * NSEQ + n0;
            #pragma unroll
            for (int wi = 0; wi < 2; wi++) {
                int pos = ((lane >> 3) << 3) | permw(lane & 7);
                unsigned word = sTw[row * 68 + wi * 32 + lane];
                *(unsigned*)&g_vt[basev + wi * 64 + pos * 2] = word;
            }
        }
    }
}

// --------------------------------------------------------------------------
// Kernel 2: flash attention — R9 body verbatim (proven fastest: 113.2us).
// --------------------------------------------------------------------------
#define KPW 24
#define VPW 40
#define KT_W (64 * KPW)
#define VT_W (40 * VPW)        // rows 32..39 = ones/zeros helper

__global__ __launch_bounds__(128) void attn_kernel()
{
    __shared__ unsigned Kb[2 * KT_W];
    __shared__ unsigned Vb[2 * VT_W];

    const int tid = threadIdx.x;
    const int wp = tid >> 5, lane = tid & 31;
    const int g = lane >> 2, t = lane & 3;
    const int qt = blockIdx.x, bh = blockIdx.y;

    const int r0 = qt * 64 + wp * 16 + g;
    const int r1 = r0 + 8;

    // helper rows (32..39) in both V buffers: row 32 = 1.0h pairs, rest 0
    #pragma unroll
    for (int i = tid; i < 2 * 8 * 32; i += 128) {
        int buf = i >> 8, rem = i & 255;
        int r = rem >> 5, c = rem & 31;
        Vb[buf * VT_W + (32 + r) * VPW + c] = (r == 0) ? 0x3C003C00u : 0u;
    }

    // Q fragments: permuted words -> one uint2 per (kc, row)
    unsigned qa[2][4];
    {
        const unsigned* q0 = g_qw + ((size_t)bh * NSEQ + r0) * 16;
        const unsigned* q1 = g_qw + ((size_t)bh * NSEQ + r1) * 16;
        #pragma unroll
        for (int kc = 0; kc < 2; kc++) {
            uint2 lo = *(const uint2*)&q0[kc * 8 + 2 * t];
            uint2 hi = *(const uint2*)&q1[kc * 8 + 2 * t];
            qa[kc][0] = lo.x; qa[kc][1] = hi.x;
            qa[kc][2] = lo.y; qa[kc][3] = hi.y;
        }
    }

    float o[5][4];
    #pragma unroll
    for (int nt = 0; nt < 5; nt++)
        #pragma unroll
        for (int j = 0; j < 4; j++) o[nt][j] = 0.f;

    const unsigned* mrow0 = &g_mask[(size_t)r0 * 64];
    const unsigned* mrow1 = &g_mask[(size_t)r1 * 64];
    const unsigned* kbase = g_kw + (size_t)bh * NSEQ * 16;
    const unsigned* vbase = (const unsigned*)g_vt + (size_t)bh * DHEAD * (NSEQ / 2);

    auto stageK = [&](int buf, int ktile) {
        const unsigned* kg = kbase + (size_t)ktile * 64 * 16;
        unsigned* kd = Kb + buf * KT_W;
        #pragma unroll
        for (int i = tid; i < 256; i += 128) {
            int r = i >> 2, c = (i & 3) * 4;
            cpa16(&kd[r * KPW + c], kg + r * 16 + c);
        }
        asm volatile("cp.async.commit_group;" ::: "memory");
    };
    auto stageV = [&](int buf, int ktile) {
        const unsigned* vg = vbase + (size_t)ktile * 32;
        unsigned* vd = Vb + buf * VT_W;
        #pragma unroll
        for (int i = tid; i < 256; i += 128) {
            int r = i >> 3, c = (i & 7) * 4;
            cpa16(&vd[r * VPW + c], vg + (size_t)r * (NSEQ / 2) + c);
        }
        asm volatile("cp.async.commit_group;" ::: "memory");
    };

    // Prologue: K0,V0,K1 staged; QK(0) issued before the loop.
    stageK(0, 0);
    stageV(0, 0);
    stageK(1, 1);
    asm volatile("cp.async.wait_group 0;" ::: "memory");
    __syncthreads();

    float s[8][4];
    #pragma unroll
    for (int nt = 0; nt < 8; nt++)
        #pragma unroll
        for (int j = 0; j < 4; j++) s[nt][j] = -EOFF;
    {
        const unsigned* Ks = Kb;
        #pragma unroll
        for (int kc = 0; kc < 2; kc++)
            #pragma unroll
            for (int nt = 0; nt < 8; nt++) {
                uint2 kk = *(const uint2*)&Ks[(nt * 8 + g) * KPW + kc * 8 + 2 * t];
                mma16(s[nt], qa[kc][0], qa[kc][1], qa[kc][2], qa[kc][3], kk.x, kk.y);
            }
    }

    for (int kt = 0; kt < NT; kt++) {
        __syncthreads();
        if (kt + 2 < NT) stageK(kt & 1, kt + 2);
        if (kt + 1 < NT) stageV((kt + 1) & 1, kt + 1);
        if (kt + 2 < NT)      asm volatile("cp.async.wait_group 2;" ::: "memory");
        else if (kt + 1 < NT) asm volatile("cp.async.wait_group 1;" ::: "memory");
        else                  asm volatile("cp.async.wait_group 0;" ::: "memory");
        __syncthreads();

        // ---- mask (fp32 additive), then f16x2 cvt+exp2 -> packed P words
        uint2 mw0 = *(const uint2*)&mrow0[kt * 2];
        uint2 mw1 = *(const uint2*)&mrow1[kt * 2];
        #pragma unroll
        for (int nt = 0; nt < 8; nt++) {
            int sh = (nt * 8 + 2 * t) & 31;
            unsigned w0 = (nt < 4) ? mw0.x : mw0.y;
            unsigned w1 = (nt < 4) ? mw1.x : mw1.y;
            if (!((w0 >> sh) & 1))       s[nt][0] += NEGV;
            if (!((w0 >> (sh + 1)) & 1)) s[nt][1] += NEGV;
            if (!((w1 >> sh) & 1))       s[nt][2] += NEGV;
            if (!((w1 >> (sh + 1)) & 1)) s[nt][3] += NEGV;
        }
        unsigned pa[4][4];
        #pragma unroll
        for (int j = 0; j < 4; j++) {
            pa[j][0] = ex2_h2(cvt_h2(s[2*j][0],   s[2*j][1]));
            pa[j][1] = ex2_h2(cvt_h2(s[2*j][2],   s[2*j][3]));
            pa[j][2] = ex2_h2(cvt_h2(s[2*j+1][0], s[2*j+1][1]));
            pa[j][3] = ex2_h2(cvt_h2(s[2*j+1][2], s[2*j+1][3]));
        }
        #pragma unroll
        for (int nt = 0; nt < 8; nt++)
            #pragma unroll
            for (int j = 0; j < 4; j++) s[nt][j] = -EOFF;

        // ---- interleaved dual-stream mma: 20 PV (incl. l-block nt=4)
        //      woven with 16 QK(kt+1)
        const unsigned* Kn = Kb + ((kt + 1) & 1) * KT_W;
        const unsigned* Vc = Vb + (kt & 1) * VT_W;
        if (kt + 1 < NT) {
            int qi = 0;
            #pragma unroll
            for (int step = 0; step < 20; step++) {
                {
                    int j = step / 5, nt = step % 5;
                    uint2 vv = *(const uint2*)&Vc[(nt * 8 + g) * VPW + j * 8 + 2 * t];
                    mma16(o[nt], pa[j][0], pa[j][1], pa[j][2], pa[j][3], vv.x, vv.y);
                }
                if (step % 5 != 4) {
                    int kc = qi >> 3, nt = qi & 7; qi++;
                    uint2 kk = *(const uint2*)&Kn[(nt * 8 + g) * KPW + kc * 8 + 2 * t];
                    mma16(s[nt], qa[kc][0], qa[kc][1], qa[kc][2], qa[kc][3], kk.x, kk.y);
                }
            }
        } else {
            #pragma unroll
            for (int step = 0; step < 20; step++) {
                int j = step / 5, nt = step % 5;
                uint2 vv = *(const uint2*)&Vc[(nt * 8 + g) * VPW + j * 8 + 2 * t];
                mma16(o[nt], pa[j][0], pa[j][1], pa[j][2], pa[j][3], vv.x, vv.y);
            }
        }
    }

    // epilogue: l lives in o[4][0]/o[4][2] of the t==0 lane (col 32)
    float l0 = __shfl_sync(0xffffffffu, o[4][0], lane & ~3);
    float l1 = __shfl_sync(0xffffffffu, o[4][2], lane & ~3);
    float inv0 = 1.f / l0, inv1 = 1.f / l1;

    const int b = bh >> 2, h = bh & 3;
    float* d0 = g_attn + ((size_t)b * NSEQ + r0) * EDIM + h * DHEAD;
    float* d1 = g_attn + ((size_t)b * NSEQ + r1) * EDIM + h * DHEAD;
    #pragma unroll
    for (int nt = 0; nt < 4; nt++) {
        int c = nt * 8 + 2 * t;
        *(float2*)&d0[c] = make_float2(o[nt][0] * inv0, o[nt][1] * inv0);
        *(float2*)&d1[c] = make_float2(o[nt][2] * inv1, o[nt][3] * inv1);
    }
}

// --------------------------------------------------------------------------
// Kernel 3: output projection, 256 thr, tile 128 x 64, single-shot smem load.
// --------------------------------------------------------------------------
__global__ __launch_bounds__(256) void out_proj_kernel(
    const float* __restrict__ w, const float* __restrict__ bias,
    float* __restrict__ out)
{
    extern __shared__ unsigned dsm[];
    unsigned* Xs = dsm;
    unsigned* Ws = dsm + 128 * GP;

    const int tid = threadIdx.x;
    const int wp = tid >> 5, lane = tid & 31;
    const int g = lane >> 2, t = lane & 3;
    const int m0 = blockIdx.y * 128, c0 = blockIdx.x * 64;

    float acc[8][4];
    #pragma unroll
    for (int nt = 0; nt < 8; nt++)
        #pragma unroll
        for (int j = 0; j < 4; j++) acc[nt][j] = 0.f;

    gemm_body(Xs, Ws, g_attn, w, m0, c0, tid, wp, g, t, acc);

    const int mrow0 = m0 + wp * 16 + g;
    #pragma unroll
    for (int nt = 0; nt < 8; nt++) {
        int cg = c0 + nt * 8 + 2 * t;
        float b0v = bias[cg], b1v = bias[cg + 1];
        #pragma unroll
        for (int rr = 0; rr < 2; rr++) {
            int m = mrow0 + rr * 8;
            *(float2*)&out[(size_t)m * EDIM + cg] =
                make_float2(acc[nt][rr * 2 + 0] + b0v, acc[nt][rr * 2 + 1] + b1v);
        }
    }
}

// --------------------------------------------------------------------------
extern "C" void kernel_launch(void* const* d_in, const int* in_sizes, int n_in,
                              void* d_out, int out_size)
{
    const float* x   = (const float*)d_in[0];
    const int*   adj = (const int*)  d_in[1];
    const float* ipw = (const float*)d_in[2];
    const float* ipb = (const float*)d_in[3];
    const float* ow  = (const float*)d_in[4];
    const float* ob  = (const float*)d_in[5];
    float* out = (float*)d_out;

    (void)in_sizes; (void)n_in; (void)out_size;

    // opt-in to >48KB dynamic smem (host-side attribute; capture-safe)
    cudaFuncSetAttribute(qkv_proj_kernel,
                         cudaFuncAttributeMaxDynamicSharedMemorySize,
                         GEMM_SMEM_BYTES);
    cudaFuncSetAttribute(out_proj_kernel,
                         cudaFuncAttributeMaxDynamicSharedMemorySize,
                         GEMM_SMEM_BYTES);

    maskpack_kernel<<<16384, 256>>>(adj);
    qkv_proj_kernel<<<dim3(6, 128), 256, GEMM_SMEM_BYTES>>>(x, ipw, ipb);
    attn_kernel<<<dim3(32, 32), 128>>>();
    out_proj_kernel<<<dim3(2, 128), 256, GEMM_SMEM_BYTES>>>(ow, ob, out);
}

// round 15
// speedup vs baseline: 1.2169x; 1.2169x over previous
#include <cuda_runtime.h>
#include <cuda_fp16.h>
#include <cstdint>

#define BSZ   8
#define NSEQ  2048
#define EDIM  128
#define HEADS 4
#define DHEAD 32
#define NEGV  -1e9f
#define QS2    0.25503482120645087f          // (1/sqrt(32)) * log2(e)
#define EOFF   6.0f                          // fixed exponent offset (log2 domain)
#define NT     (NSEQ / 64)                   // 32 kv tiles

// Scratch. Q/K d-words and Vt kv-words are PERMUTED within 8-word groups
// (perm(x) = 2*(x&3) + (x>>2)) so mma B/A fragment pairs (t, t+4) are
// physically adjacent -> single LDS.64 / LDG.64.
__device__ unsigned g_qw[(size_t)BSZ * HEADS * NSEQ * (DHEAD / 2)];
__device__ unsigned g_kw[(size_t)BSZ * HEADS * NSEQ * (DHEAD / 2)];
__device__ __half   g_vt[(size_t)BSZ * HEADS * DHEAD * NSEQ];
__device__ float    g_attn[(size_t)BSZ * NSEQ * EDIM];
__device__ unsigned g_mask[(size_t)NSEQ * (NSEQ / 32)];

// --------------------------------------------------------------------------
__device__ __forceinline__ unsigned f2tf(float f) {
    unsigned r; asm("cvt.rna.tf32.f32 %0, %1;" : "=r"(r) : "f"(f)); return r;
}
__device__ __forceinline__ unsigned packh2(float a, float b) {
    __half2 h = __floats2half2_rn(a, b); return *(unsigned*)&h;
}
__device__ __forceinline__ unsigned cvt_h2(float a, float b) {
    unsigned r;
    asm("cvt.rn.f16x2.f32 %0, %1, %2;" : "=r"(r) : "f"(b), "f"(a));
    return r;
}
__device__ __forceinline__ unsigned ex2_h2(unsigned x) {
    unsigned r;
    asm("ex2.approx.f16x2 %0, %1;" : "=r"(r) : "r"(x));
    return r;
}
__device__ __forceinline__ void mma8(float* c,
                                     unsigned a0, unsigned a1, unsigned a2, unsigned a3,
                                     unsigned b0, unsigned b1) {
    asm volatile(
        "mma.sync.aligned.m16n8k8.row.col.f32.tf32.tf32.f32 "
        "{%0,%1,%2,%3}, {%4,%5,%6,%7}, {%8,%9}, {%0,%1,%2,%3};"
        : "+f"(c[0]), "+f"(c[1]), "+f"(c[2]), "+f"(c[3])
        : "r"(a0), "r"(a1), "r"(a2), "r"(a3), "r"(b0), "r"(b1));
}
__device__ __forceinline__ void mma16(float* c,
                                      unsigned a0, unsigned a1, unsigned a2, unsigned a3,
                                      unsigned b0, unsigned b1) {
    asm volatile(
        "mma.sync.aligned.m16n8k16.row.col.f32.f16.f16.f32 "
        "{%0,%1,%2,%3}, {%4,%5,%6,%7}, {%8,%9}, {%0,%1,%2,%3};"
        : "+f"(c[0]), "+f"(c[1]), "+f"(c[2]), "+f"(c[3])
        : "r"(a0), "r"(a1), "r"(a2), "r"(a3), "r"(b0), "r"(b1));
}
__device__ __forceinline__ void cpa16(void* dst, const void* src) {
    unsigned d = (unsigned)__cvta_generic_to_shared(dst);
    asm volatile("cp.async.ca.shared.global [%0], [%1], 16;" :: "r"(d), "l"(src));
}
__device__ __forceinline__ int permw(int x) { return 2 * (x & 3) + (x >> 2); }

// --------------------------------------------------------------------------
// Kernel 0: bit-pack adj[0]
// --------------------------------------------------------------------------
__global__ __launch_bounds__(256) void maskpack_kernel(const int* __restrict__ adj) {
    int gid  = blockIdx.x * 256 + threadIdx.x;
    int w    = gid >> 5;
    int lane = gid & 31;
    int n    = w >> 6;
    int word = w & 63;
    int v = adj[(size_t)n * NSEQ + word * 32 + lane];
    unsigned m = __ballot_sync(0xffffffffu, v != 0);
    if (lane == 0) g_mask[w] = m;
}

// --------------------------------------------------------------------------
// Kernel 1: QKV projection (tf32 mma), 256 thr, tile 128 x 64, K-loop form
// (proven in the 113.2us build).  ONLY change vs that build: V blocks
// (c0 >= 256) stage through smem and write transposed, permuted words with
// coalesced 4B stores (replaces 2B stride-4KB scatter; validated in R10).
// --------------------------------------------------------------------------
__global__ __launch_bounds__(256) void qkv_proj_kernel(
    const float* __restrict__ x, const float* __restrict__ w,
    const float* __restrict__ bias)
{
    __shared__ unsigned Xs[128 * 36];
    __shared__ unsigned Ws[64 * 36];

    const int tid = threadIdx.x;
    const int wp = tid >> 5, lane = tid & 31;
    const int g = lane >> 2, t = lane & 3;
    const int m0 = blockIdx.y * 128, c0 = blockIdx.x * 64;

    float acc[8][4];
    #pragma unroll
    for (int nt = 0; nt < 8; nt++)
        #pragma unroll
        for (int j = 0; j < 4; j++) acc[nt][j] = 0.f;

    for (int ko = 0; ko < EDIM; ko += 32) {
        __syncthreads();
        #pragma unroll
        for (int i = tid; i < 1024; i += 256) {
            int r = i >> 3, c4 = (i & 7) * 4;
            float4 v4 = *(const float4*)&x[(size_t)(m0 + r) * EDIM + ko + c4];
            *(uint4*)&Xs[r * 36 + c4] =
                make_uint4(f2tf(v4.x), f2tf(v4.y), f2tf(v4.z), f2tf(v4.w));
        }
        #pragma unroll
        for (int i = tid; i < 512; i += 256) {
            int r = i >> 3, c4 = (i & 7) * 4;
            float4 w4 = *(const float4*)&w[(size_t)(c0 + r) * EDIM + ko + c4];
            *(uint4*)&Ws[r * 36 + c4] =
                make_uint4(f2tf(w4.x), f2tf(w4.y), f2tf(w4.z), f2tf(w4.w));
        }
        __syncthreads();

        #pragma unroll
        for (int kc = 0; kc < 4; kc++) {
            const unsigned* xr = &Xs[(wp * 16 + g) * 36 + kc * 8 + t];
            unsigned a0 = xr[0], a1 = xr[8 * 36], a2 = xr[4], a3 = xr[8 * 36 + 4];
            #pragma unroll
            for (int nt = 0; nt < 8; nt++) {
                unsigned b0 = Ws[(nt * 8 + g) * 36 + kc * 8 + t];
                unsigned b1 = Ws[(nt * 8 + g) * 36 + kc * 8 + t + 4];
                mma8(acc[nt], a0, a1, a2, a3, b0, b1);
            }
        }
    }

    const int bb = m0 >> 11;
    const int n0 = m0 & (NSEQ - 1);
    const int mrow0 = m0 + wp * 16 + g;

    if (c0 < 256) {
        // ---- Q / K epilogue (permuted half2 words) — unchanged
        #pragma unroll
        for (int nt = 0; nt < 8; nt++) {
            int cg = c0 + nt * 8 + 2 * t;
            float b0v = bias[cg], b1v = bias[cg + 1];
            int part = cg >> 7;
            int e = cg & 127, hh = e >> 5, d0 = e & 31;
            int wrd = d0 >> 1;
            int wperm = (wrd & ~7) | permw(wrd & 7);
            #pragma unroll
            for (int rr = 0; rr < 2; rr++) {
                int m = mrow0 + rr * 8;
                int bbm = m >> 11, n = m & (NSEQ - 1);
                int bh = bbm * HEADS + hh;
                float v0 = acc[nt][rr * 2 + 0] + b0v;
                float v1 = acc[nt][rr * 2 + 1] + b1v;
                if (part == 0) {
                    g_qw[((size_t)bh * NSEQ + n) * 16 + wperm] =
                        packh2(v0 * QS2, v1 * QS2);
                } else {
                    g_kw[((size_t)bh * NSEQ + n) * 16 + wperm] = packh2(v0, v1);
                }
            }
        }
    } else {
        // ---- V epilogue: stage [e][n] tile in smem, write coalesced
        __syncthreads();            // done reading Xs in mma loop
        __half* sT = (__half*)Xs;   // 64 x 136 halves = 17408 B (fits in Xs)
        #pragma unroll
        for (int nt = 0; nt < 8; nt++) {
            int cg = c0 + nt * 8 + 2 * t;
            float b0v = bias[cg], b1v = bias[cg + 1];
            int e0 = nt * 8 + 2 * t;   // block-local e (0..63)
            #pragma unroll
            for (int rr = 0; rr < 2; rr++) {
                int nl = wp * 16 + g + rr * 8;   // block-local n (0..127)
                sT[(e0)     * 136 + nl] = __float2half_rn(acc[nt][rr * 2 + 0] + b0v);
                sT[(e0 + 1) * 136 + nl] = __float2half_rn(acc[nt][rr * 2 + 1] + b1v);
            }
        }
        __syncthreads();

        const unsigned* sTw = (const unsigned*)sT;   // row stride 68 words
        const int ebase = c0 - 256;                  // 0 or 64
        #pragma unroll
        for (int r8 = 0; r8 < 8; r8++) {
            int row = wp * 8 + r8;                   // 0..63
            int e = ebase + row;
            int h = e >> 5, d0v = e & 31;
            size_t basev = ((size_t)(bb * HEADS + h) * DHEAD + d0v) * NSEQ + n0;
            #pragma unroll
            for (int wi = 0; wi < 2; wi++) {
                int pos = ((lane >> 3) << 3) | permw(lane & 7);  // permuted word
                unsigned word = sTw[row * 68 + wi * 32 + lane];
                *(unsigned*)&g_vt[basev + wi * 64 + pos * 2] = word;
            }
        }
    }
}

// --------------------------------------------------------------------------
// Kernel 2: flash attention — the proven 113.2us body VERBATIM.
// fp16 mma, pipelined QK(kt+1)/PV(kt), s init -EOFF, f16x2 cvt+ex2,
// l via helper ones-rows in Vt (PV mma accumulates it), LDS.64 fragments.
// 128 thr (4 warps), 64 q rows/block, 64 kv/iter, grid (32, 32).
// --------------------------------------------------------------------------
#define KPW 24                 // K smem pitch (16 data + 8 pad)
#define VPW 40                 // Vt smem pitch (32 data + 8 pad)
#define KT_W (64 * KPW)
#define VT_W (40 * VPW)        // rows 32..39 = ones/zeros helper

__global__ __launch_bounds__(128) void attn_kernel()
{
    __shared__ unsigned Kb[2 * KT_W];
    __shared__ unsigned Vb[2 * VT_W];

    const int tid = threadIdx.x;
    const int wp = tid >> 5, lane = tid & 31;
    const int g = lane >> 2, t = lane & 3;
    const int qt = blockIdx.x, bh = blockIdx.y;

    const int r0 = qt * 64 + wp * 16 + g;
    const int r1 = r0 + 8;

    // helper rows (32..39) in both V buffers: row 32 = 1.0h pairs, rest 0
    #pragma unroll
    for (int i = tid; i < 2 * 8 * 32; i += 128) {
        int buf = i >> 8, rem = i & 255;
        int r = rem >> 5, c = rem & 31;
        Vb[buf * VT_W + (32 + r) * VPW + c] = (r == 0) ? 0x3C003C00u : 0u;
    }

    // Q fragments: permuted words -> one uint2 per (kc, row)
    unsigned qa[2][4];
    {
        const unsigned* q0 = g_qw + ((size_t)bh * NSEQ + r0) * 16;
        const unsigned* q1 = g_qw + ((size_t)bh * NSEQ + r1) * 16;
        #pragma unroll
        for (int kc = 0; kc < 2; kc++) {
            uint2 lo = *(const uint2*)&q0[kc * 8 + 2 * t];
            uint2 hi = *(const uint2*)&q1[kc * 8 + 2 * t];
            qa[kc][0] = lo.x; qa[kc][1] = hi.x;
            qa[kc][2] = lo.y; qa[kc][3] = hi.y;
        }
    }

    float o[5][4];
    #pragma unroll
    for (int nt = 0; nt < 5; nt++)
        #pragma unroll
        for (int j = 0; j < 4; j++) o[nt][j] = 0.f;

    const unsigned* mrow0 = &g_mask[(size_t)r0 * 64];
    const unsigned* mrow1 = &g_mask[(size_t)r1 * 64];
    const unsigned* kbase = g_kw + (size_t)bh * NSEQ * 16;
    const unsigned* vbase = (const unsigned*)g_vt + (size_t)bh * DHEAD * (NSEQ / 2);

    auto stageK = [&](int buf, int ktile) {
        const unsigned* kg = kbase + (size_t)ktile * 64 * 16;
        unsigned* kd = Kb + buf * KT_W;
        #pragma unroll
        for (int i = tid; i < 256; i += 128) {
            int r = i >> 2, c = (i & 3) * 4;
            cpa16(&kd[r * KPW + c], kg + r * 16 + c);
        }
        asm volatile("cp.async.commit_group;" ::: "memory");
    };
    auto stageV = [&](int buf, int ktile) {
        const unsigned* vg = vbase + (size_t)ktile * 32;
        unsigned* vd = Vb + buf * VT_W;
        #pragma unroll
        for (int i = tid; i < 256; i += 128) {
            int r = i >> 3, c = (i & 7) * 4;
            cpa16(&vd[r * VPW + c], vg + (size_t)r * (NSEQ / 2) + c);
        }
        asm volatile("cp.async.commit_group;" ::: "memory");
    };

    // Prologue: K0,V0,K1 staged; QK(0) issued before the loop.
    stageK(0, 0);
    stageV(0, 0);
    stageK(1, 1);
    asm volatile("cp.async.wait_group 0;" ::: "memory");
    __syncthreads();

    float s[8][4];
    #pragma unroll
    for (int nt = 0; nt < 8; nt++)
        #pragma unroll
        for (int j = 0; j < 4; j++) s[nt][j] = -EOFF;
    {
        const unsigned* Ks = Kb;
        #pragma unroll
        for (int kc = 0; kc < 2; kc++)
            #pragma unroll
            for (int nt = 0; nt < 8; nt++) {
                uint2 kk = *(const uint2*)&Ks[(nt * 8 + g) * KPW + kc * 8 + 2 * t];
                mma16(s[nt], qa[kc][0], qa[kc][1], qa[kc][2], qa[kc][3], kk.x, kk.y);
            }
    }

    for (int kt = 0; kt < NT; kt++) {
        __syncthreads();
        if (kt + 2 < NT) stageK(kt & 1, kt + 2);
        if (kt + 1 < NT) stageV((kt + 1) & 1, kt + 1);
        if (kt + 2 < NT)      asm volatile("cp.async.wait_group 2;" ::: "memory");
        else if (kt + 1 < NT) asm volatile("cp.async.wait_group 1;" ::: "memory");
        else                  asm volatile("cp.async.wait_group 0;" ::: "memory");
        __syncthreads();

        // ---- mask (fp32 additive), then f16x2 cvt+exp2 -> packed P words
        uint2 mw0 = *(const uint2*)&mrow0[kt * 2];
        uint2 mw1 = *(const uint2*)&mrow1[kt * 2];
        #pragma unroll
        for (int nt = 0; nt < 8; nt++) {
            int sh = (nt * 8 + 2 * t) & 31;
            unsigned w0 = (nt < 4) ? mw0.x : mw0.y;
            unsigned w1 = (nt < 4) ? mw1.x : mw1.y;
            if (!((w0 >> sh) & 1))       s[nt][0] += NEGV;
            if (!((w0 >> (sh + 1)) & 1)) s[nt][1] += NEGV;
            if (!((w1 >> sh) & 1))       s[nt][2] += NEGV;
            if (!((w1 >> (sh + 1)) & 1)) s[nt][3] += NEGV;
        }
        unsigned pa[4][4];
        #pragma unroll
        for (int j = 0; j < 4; j++) {
            pa[j][0] = ex2_h2(cvt_h2(s[2*j][0],   s[2*j][1]));
            pa[j][1] = ex2_h2(cvt_h2(s[2*j][2],   s[2*j][3]));
            pa[j][2] = ex2_h2(cvt_h2(s[2*j+1][0], s[2*j+1][1]));
            pa[j][3] = ex2_h2(cvt_h2(s[2*j+1][2], s[2*j+1][3]));
        }
        #pragma unroll
        for (int nt = 0; nt < 8; nt++)
            #pragma unroll
            for (int j = 0; j < 4; j++) s[nt][j] = -EOFF;

        // ---- interleaved dual-stream mma: 20 PV (incl. l-block nt=4)
        //      woven with 16 QK(kt+1)
        const unsigned* Kn = Kb + ((kt + 1) & 1) * KT_W;
        const unsigned* Vc = Vb + (kt & 1) * VT_W;
        if (kt + 1 < NT) {
            int qi = 0;
            #pragma unroll
            for (int step = 0; step < 20; step++) {
                {
                    int j = step / 5, nt = step % 5;
                    uint2 vv = *(const uint2*)&Vc[(nt * 8 + g) * VPW + j * 8 + 2 * t];
                    mma16(o[nt], pa[j][0], pa[j][1], pa[j][2], pa[j][3], vv.x, vv.y);
                }
                if (step % 5 != 4) {
                    int kc = qi >> 3, nt = qi & 7; qi++;
                    uint2 kk = *(const uint2*)&Kn[(nt * 8 + g) * KPW + kc * 8 + 2 * t];
                    mma16(s[nt], qa[kc][0], qa[kc][1], qa[kc][2], qa[kc][3], kk.x, kk.y);
                }
            }
        } else {
            #pragma unroll
            for (int step = 0; step < 20; step++) {
                int j = step / 5, nt = step % 5;
                uint2 vv = *(const uint2*)&Vc[(nt * 8 + g) * VPW + j * 8 + 2 * t];
                mma16(o[nt], pa[j][0], pa[j][1], pa[j][2], pa[j][3], vv.x, vv.y);
            }
        }
    }

    // epilogue: l lives in o[4][0]/o[4][2] of the t==0 lane (col 32)
    float l0 = __shfl_sync(0xffffffffu, o[4][0], lane & ~3);
    float l1 = __shfl_sync(0xffffffffu, o[4][2], lane & ~3);
    float inv0 = 1.f / l0, inv1 = 1.f / l1;

    const int b = bh >> 2, h = bh & 3;
    float* d0 = g_attn + ((size_t)b * NSEQ + r0) * EDIM + h * DHEAD;
    float* d1 = g_attn + ((size_t)b * NSEQ + r1) * EDIM + h * DHEAD;
    #pragma unroll
    for (int nt = 0; nt < 4; nt++) {
        int c = nt * 8 + 2 * t;
        *(float2*)&d0[c] = make_float2(o[nt][0] * inv0, o[nt][1] * inv0);
        *(float2*)&d1[c] = make_float2(o[nt][2] * inv1, o[nt][3] * inv1);
    }
}

// --------------------------------------------------------------------------
// Kernel 3: output projection (tf32 mma), 256 thr, tile 128 x 64,
// K-loop form — verbatim from the 113.2us build.
// --------------------------------------------------------------------------
__global__ __launch_bounds__(256) void out_proj_kernel(
    const float* __restrict__ w, const float* __restrict__ bias,
    float* __restrict__ out)
{
    __shared__ unsigned Xs[128 * 36];
    __shared__ unsigned Ws[64 * 36];

    const int tid = threadIdx.x;
    const int wp = tid >> 5, lane = tid & 31;
    const int g = lane >> 2, t = lane & 3;
    const int m0 = blockIdx.y * 128, c0 = blockIdx.x * 64;

    float acc[8][4];
    #pragma unroll
    for (int nt = 0; nt < 8; nt++)
        #pragma unroll
        for (int j = 0; j < 4; j++) acc[nt][j] = 0.f;

    for (int ko = 0; ko < EDIM; ko += 32) {
        __syncthreads();
        #pragma unroll
        for (int i = tid; i < 1024; i += 256) {
            int r = i >> 3, c4 = (i & 7) * 4;
            float4 v4 = *(const float4*)&g_attn[(size_t)(m0 + r) * EDIM + ko + c4];
            *(uint4*)&Xs[r * 36 + c4] =
                make_uint4(f2tf(v4.x), f2tf(v4.y), f2tf(v4.z), f2tf(v4.w));
        }
        #pragma unroll
        for (int i = tid; i < 512; i += 256) {
            int r = i >> 3, c4 = (i & 7) * 4;
            float4 w4 = *(const float4*)&w[(size_t)(c0 + r) * EDIM + ko + c4];
            *(uint4*)&Ws[r * 36 + c4] =
                make_uint4(f2tf(w4.x), f2tf(w4.y), f2tf(w4.z), f2tf(w4.w));
        }
        __syncthreads();

        #pragma unroll
        for (int kc = 0; kc < 4; kc++) {
            const unsigned* xr = &Xs[(wp * 16 + g) * 36 + kc * 8 + t];
            unsigned a0 = xr[0], a1 = xr[8 * 36], a2 = xr[4], a3 = xr[8 * 36 + 4];
            #pragma unroll
            for (int nt = 0; nt < 8; nt++) {
                unsigned b0 = Ws[(nt * 8 + g) * 36 + kc * 8 + t];
                unsigned b1 = Ws[(nt * 8 + g) * 36 + kc * 8 + t + 4];
                mma8(acc[nt], a0, a1, a2, a3, b0, b1);
            }
        }
    }

    const int mrow0 = m0 + wp * 16 + g;
    #pragma unroll
    for (int nt = 0; nt < 8; nt++) {
        int cg = c0 + nt * 8 + 2 * t;
        float b0v = bias[cg], b1v = bias[cg + 1];
        #pragma unroll
        for (int rr = 0; rr < 2; rr++) {
            int m = mrow0 + rr * 8;
            *(float2*)&out[(size_t)m * EDIM + cg] =
                make_float2(acc[nt][rr * 2 + 0] + b0v, acc[nt][rr * 2 + 1] + b1v);
        }
    }
}

// --------------------------------------------------------------------------
extern "C" void kernel_launch(void* const* d_in, const int* in_sizes, int n_in,
                              void* d_out, int out_size)
{
    const float* x   = (const float*)d_in[0];
    const int*   adj = (const int*)  d_in[1];
    const float* ipw = (const float*)d_in[2];
    const float* ipb = (const float*)d_in[3];
    const float* ow  = (const float*)d_in[4];
    const float* ob  = (const float*)d_in[5];
    float* out = (float*)d_out;

    (void)in_sizes; (void)n_in; (void)out_size;

    maskpack_kernel<<<16384, 256>>>(adj);
    qkv_proj_kernel<<<dim3(6, 128), 256>>>(x, ipw, ipb);
    attn_kernel<<<dim3(32, 32), 128>>>();
    out_proj_kernel<<<dim3(2, 128), 256>>>(ow, ob, out);
}

// round 16
// speedup vs baseline: 1.2326x; 1.0129x over previous
#include <cuda_runtime.h>
#include <cuda_fp16.h>
#include <cstdint>

#define BSZ   8
#define NSEQ  2048
#define EDIM  128
#define HEADS 4
#define DHEAD 32
#define NEGV  -1e9f
#define QS2    0.25503482120645087f          // (1/sqrt(32)) * log2(e)
#define EOFF   6.0f                          // fixed exponent offset (log2 domain)
#define NT     (NSEQ / 64)                   // 32 kv tiles

// Scratch. Q/K d-words and Vt kv-words are PERMUTED within 8-word groups
// (perm(x) = 2*(x&3) + (x>>2)) so mma B/A fragment pairs (t, t+4) are
// physically adjacent -> single LDS.64 / LDG.64.
__device__ unsigned g_qw[(size_t)BSZ * HEADS * NSEQ * (DHEAD / 2)];
__device__ unsigned g_kw[(size_t)BSZ * HEADS * NSEQ * (DHEAD / 2)];
__device__ __half   g_vt[(size_t)BSZ * HEADS * DHEAD * NSEQ];
__device__ float    g_attn[(size_t)BSZ * NSEQ * EDIM];
__device__ unsigned g_mask[(size_t)NSEQ * (NSEQ / 32)];

// --------------------------------------------------------------------------
__device__ __forceinline__ unsigned f2tf(float f) {
    unsigned r; asm("cvt.rna.tf32.f32 %0, %1;" : "=r"(r) : "f"(f)); return r;
}
__device__ __forceinline__ unsigned packh2(float a, float b) {
    __half2 h = __floats2half2_rn(a, b); return *(unsigned*)&h;
}
__device__ __forceinline__ unsigned cvt_h2(float a, float b) {
    unsigned r;
    asm("cvt.rn.f16x2.f32 %0, %1, %2;" : "=r"(r) : "f"(b), "f"(a));
    return r;
}
__device__ __forceinline__ unsigned ex2_h2(unsigned x) {
    unsigned r;
    asm("ex2.approx.f16x2 %0, %1;" : "=r"(r) : "r"(x));
    return r;
}
__device__ __forceinline__ void mma8(float* c,
                                     unsigned a0, unsigned a1, unsigned a2, unsigned a3,
                                     unsigned b0, unsigned b1) {
    asm volatile(
        "mma.sync.aligned.m16n8k8.row.col.f32.tf32.tf32.f32 "
        "{%0,%1,%2,%3}, {%4,%5,%6,%7}, {%8,%9}, {%0,%1,%2,%3};"
        : "+f"(c[0]), "+f"(c[1]), "+f"(c[2]), "+f"(c[3])
        : "r"(a0), "r"(a1), "r"(a2), "r"(a3), "r"(b0), "r"(b1));
}
__device__ __forceinline__ void mma16(float* c,
                                      unsigned a0, unsigned a1, unsigned a2, unsigned a3,
                                      unsigned b0, unsigned b1) {
    asm volatile(
        "mma.sync.aligned.m16n8k16.row.col.f32.f16.f16.f32 "
        "{%0,%1,%2,%3}, {%4,%5,%6,%7}, {%8,%9}, {%0,%1,%2,%3};"
        : "+f"(c[0]), "+f"(c[1]), "+f"(c[2]), "+f"(c[3])
        : "r"(a0), "r"(a1), "r"(a2), "r"(a3), "r"(b0), "r"(b1));
}
__device__ __forceinline__ void cpa16(void* dst, const void* src) {
    unsigned d = (unsigned)__cvta_generic_to_shared(dst);
    asm volatile("cp.async.ca.shared.global [%0], [%1], 16;" :: "r"(d), "l"(src));
}
__device__ __forceinline__ int permw(int x) { return 2 * (x & 3) + (x >> 2); }

// --------------------------------------------------------------------------
// Kernel 0: bit-pack adj[0]
// --------------------------------------------------------------------------
__global__ __launch_bounds__(256) void maskpack_kernel(const int* __restrict__ adj) {
    int gid  = blockIdx.x * 256 + threadIdx.x;
    int w    = gid >> 5;
    int lane = gid & 31;
    int n    = w >> 6;
    int word = w & 63;
    int v = adj[(size_t)n * NSEQ + word * 32 + lane];
    unsigned m = __ballot_sync(0xffffffffu, v != 0);
    if (lane == 0) g_mask[w] = m;
}

// --------------------------------------------------------------------------
// Register-staged pipelined GEMM K-loop (shared by both projections):
// prefetch tile ko+1 into REGISTERS between the STS of tile ko and its mma
// stream -> the global-load latency overlaps the mma work instead of
// serializing 4x per block.  Same smem layout / numerics as the R15 build.
// --------------------------------------------------------------------------
__device__ __forceinline__ void gemm_kloop_pipelined(
    unsigned* Xs, unsigned* Ws,
    const float* __restrict__ a_src, const float* __restrict__ b_src,
    int m0, int c0, int tid, int wp, int g, int t, float acc[8][4])
{
    float4 xr4[4];
    float4 wr4[2];

    // prologue: load tile ko=0 into registers
    #pragma unroll
    for (int u = 0; u < 4; u++) {
        int i = tid + u * 256;
        int r = i >> 3, c4 = (i & 7) * 4;
        xr4[u] = *(const float4*)&a_src[(size_t)(m0 + r) * EDIM + c4];
    }
    #pragma unroll
    for (int u = 0; u < 2; u++) {
        int i = tid + u * 256;
        int r = i >> 3, c4 = (i & 7) * 4;
        wr4[u] = *(const float4*)&b_src[(size_t)(c0 + r) * EDIM + c4];
    }

    #pragma unroll
    for (int ko = 0; ko < 4; ko++) {
        if (ko) __syncthreads();   // previous mma done reading smem

        // STS current tile (tf32-rounded)
        #pragma unroll
        for (int u = 0; u < 4; u++) {
            int i = tid + u * 256;
            int r = i >> 3, c4 = (i & 7) * 4;
            *(uint4*)&Xs[r * 36 + c4] =
                make_uint4(f2tf(xr4[u].x), f2tf(xr4[u].y),
                           f2tf(xr4[u].z), f2tf(xr4[u].w));
        }
        #pragma unroll
        for (int u = 0; u < 2; u++) {
            int i = tid + u * 256;
            int r = i >> 3, c4 = (i & 7) * 4;
            *(uint4*)&Ws[r * 36 + c4] =
                make_uint4(f2tf(wr4[u].x), f2tf(wr4[u].y),
                           f2tf(wr4[u].z), f2tf(wr4[u].w));
        }

        // prefetch NEXT tile into registers (latency hidden behind mma)
        if (ko < 3) {
            int kb = (ko + 1) * 32;
            #pragma unroll
            for (int u = 0; u < 4; u++) {
                int i = tid + u * 256;
                int r = i >> 3, c4 = (i & 7) * 4;
                xr4[u] = *(const float4*)&a_src[(size_t)(m0 + r) * EDIM + kb + c4];
            }
            #pragma unroll
            for (int u = 0; u < 2; u++) {
                int i = tid + u * 256;
                int r = i >> 3, c4 = (i & 7) * 4;
                wr4[u] = *(const float4*)&b_src[(size_t)(c0 + r) * EDIM + kb + c4];
            }
        }
        __syncthreads();

        // mma stream for current tile
        #pragma unroll
        for (int kc = 0; kc < 4; kc++) {
            const unsigned* xr = &Xs[(wp * 16 + g) * 36 + kc * 8 + t];
            unsigned a0 = xr[0], a1 = xr[8 * 36], a2 = xr[4], a3 = xr[8 * 36 + 4];
            #pragma unroll
            for (int nt = 0; nt < 8; nt++) {
                unsigned b0 = Ws[(nt * 8 + g) * 36 + kc * 8 + t];
                unsigned b1 = Ws[(nt * 8 + g) * 36 + kc * 8 + t + 4];
                mma8(acc[nt], a0, a1, a2, a3, b0, b1);
            }
        }
    }
}

// --------------------------------------------------------------------------
// Kernel 1: QKV projection (tf32 mma), 256 thr, tile 128 x 64, pipelined.
// --------------------------------------------------------------------------
__global__ __launch_bounds__(256) void qkv_proj_kernel(
    const float* __restrict__ x, const float* __restrict__ w,
    const float* __restrict__ bias)
{
    __shared__ unsigned Xs[128 * 36];
    __shared__ unsigned Ws[64 * 36];

    const int tid = threadIdx.x;
    const int wp = tid >> 5, lane = tid & 31;
    const int g = lane >> 2, t = lane & 3;
    const int m0 = blockIdx.y * 128, c0 = blockIdx.x * 64;

    float acc[8][4];
    #pragma unroll
    for (int nt = 0; nt < 8; nt++)
        #pragma unroll
        for (int j = 0; j < 4; j++) acc[nt][j] = 0.f;

    gemm_kloop_pipelined(Xs, Ws, x, w, m0, c0, tid, wp, g, t, acc);

    const int bb = m0 >> 11;
    const int n0 = m0 & (NSEQ - 1);
    const int mrow0 = m0 + wp * 16 + g;

    if (c0 < 256) {
        // ---- Q / K epilogue (permuted half2 words)
        #pragma unroll
        for (int nt = 0; nt < 8; nt++) {
            int cg = c0 + nt * 8 + 2 * t;
            float b0v = bias[cg], b1v = bias[cg + 1];
            int part = cg >> 7;
            int e = cg & 127, hh = e >> 5, d0 = e & 31;
            int wrd = d0 >> 1;
            int wperm = (wrd & ~7) | permw(wrd & 7);
            #pragma unroll
            for (int rr = 0; rr < 2; rr++) {
                int m = mrow0 + rr * 8;
                int bbm = m >> 11, n = m & (NSEQ - 1);
                int bh = bbm * HEADS + hh;
                float v0 = acc[nt][rr * 2 + 0] + b0v;
                float v1 = acc[nt][rr * 2 + 1] + b1v;
                if (part == 0) {
                    g_qw[((size_t)bh * NSEQ + n) * 16 + wperm] =
                        packh2(v0 * QS2, v1 * QS2);
                } else {
                    g_kw[((size_t)bh * NSEQ + n) * 16 + wperm] = packh2(v0, v1);
                }
            }
        }
    } else {
        // ---- V epilogue: stage [e][n] tile in smem, write coalesced
        __syncthreads();            // done reading Xs in mma loop
        __half* sT = (__half*)Xs;   // 64 x 136 halves = 17408 B (fits in Xs)
        #pragma unroll
        for (int nt = 0; nt < 8; nt++) {
            int cg = c0 + nt * 8 + 2 * t;
            float b0v = bias[cg], b1v = bias[cg + 1];
            int e0 = nt * 8 + 2 * t;   // block-local e (0..63)
            #pragma unroll
            for (int rr = 0; rr < 2; rr++) {
                int nl = wp * 16 + g + rr * 8;   // block-local n (0..127)
                sT[(e0)     * 136 + nl] = __float2half_rn(acc[nt][rr * 2 + 0] + b0v);
                sT[(e0 + 1) * 136 + nl] = __float2half_rn(acc[nt][rr * 2 + 1] + b1v);
            }
        }
        __syncthreads();

        const unsigned* sTw = (const unsigned*)sT;   // row stride 68 words
        const int ebase = c0 - 256;                  // 0 or 64
        #pragma unroll
        for (int r8 = 0; r8 < 8; r8++) {
            int row = wp * 8 + r8;                   // 0..63
            int e = ebase + row;
            int h = e >> 5, d0v = e & 31;
            size_t basev = ((size_t)(bb * HEADS + h) * DHEAD + d0v) * NSEQ + n0;
            #pragma unroll
            for (int wi = 0; wi < 2; wi++) {
                int pos = ((lane >> 3) << 3) | permw(lane & 7);  // permuted word
                unsigned word = sTw[row * 68 + wi * 32 + lane];
                *(unsigned*)&g_vt[basev + wi * 64 + pos * 2] = word;
            }
        }
    }
}

// --------------------------------------------------------------------------
// Kernel 2: flash attention — the proven 113.2us body VERBATIM.
// fp16 mma, pipelined QK(kt+1)/PV(kt), s init -EOFF, f16x2 cvt+ex2,
// l via helper ones-rows in Vt (PV mma accumulates it), LDS.64 fragments.
// 128 thr (4 warps), 64 q rows/block, 64 kv/iter, grid (32, 32).
// --------------------------------------------------------------------------
#define KPW 24                 // K smem pitch (16 data + 8 pad)
#define VPW 40                 // Vt smem pitch (32 data + 8 pad)
#define KT_W (64 * KPW)
#define VT_W (40 * VPW)        // rows 32..39 = ones/zeros helper

__global__ __launch_bounds__(128) void attn_kernel()
{
    __shared__ unsigned Kb[2 * KT_W];
    __shared__ unsigned Vb[2 * VT_W];

    const int tid = threadIdx.x;
    const int wp = tid >> 5, lane = tid & 31;
    const int g = lane >> 2, t = lane & 3;
    const int qt = blockIdx.x, bh = blockIdx.y;

    const int r0 = qt * 64 + wp * 16 + g;
    const int r1 = r0 + 8;

    // helper rows (32..39) in both V buffers: row 32 = 1.0h pairs, rest 0
    #pragma unroll
    for (int i = tid; i < 2 * 8 * 32; i += 128) {
        int buf = i >> 8, rem = i & 255;
        int r = rem >> 5, c = rem & 31;
        Vb[buf * VT_W + (32 + r) * VPW + c] = (r == 0) ? 0x3C003C00u : 0u;
    }

    // Q fragments: permuted words -> one uint2 per (kc, row)
    unsigned qa[2][4];
    {
        const unsigned* q0 = g_qw + ((size_t)bh * NSEQ + r0) * 16;
        const unsigned* q1 = g_qw + ((size_t)bh * NSEQ + r1) * 16;
        #pragma unroll
        for (int kc = 0; kc < 2; kc++) {
            uint2 lo = *(const uint2*)&q0[kc * 8 + 2 * t];
            uint2 hi = *(const uint2*)&q1[kc * 8 + 2 * t];
            qa[kc][0] = lo.x; qa[kc][1] = hi.x;
            qa[kc][2] = lo.y; qa[kc][3] = hi.y;
        }
    }

    float o[5][4];
    #pragma unroll
    for (int nt = 0; nt < 5; nt++)
        #pragma unroll
        for (int j = 0; j < 4; j++) o[nt][j] = 0.f;

    const unsigned* mrow0 = &g_mask[(size_t)r0 * 64];
    const unsigned* mrow1 = &g_mask[(size_t)r1 * 64];
    const unsigned* kbase = g_kw + (size_t)bh * NSEQ * 16;
    const unsigned* vbase = (const unsigned*)g_vt + (size_t)bh * DHEAD * (NSEQ / 2);

    auto stageK = [&](int buf, int ktile) {
        const unsigned* kg = kbase + (size_t)ktile * 64 * 16;
        unsigned* kd = Kb + buf * KT_W;
        #pragma unroll
        for (int i = tid; i < 256; i += 128) {
            int r = i >> 2, c = (i & 3) * 4;
            cpa16(&kd[r * KPW + c], kg + r * 16 + c);
        }
        asm volatile("cp.async.commit_group;" ::: "memory");
    };
    auto stageV = [&](int buf, int ktile) {
        const unsigned* vg = vbase + (size_t)ktile * 32;
        unsigned* vd = Vb + buf * VT_W;
        #pragma unroll
        for (int i = tid; i < 256; i += 128) {
            int r = i >> 3, c = (i & 7) * 4;
            cpa16(&vd[r * VPW + c], vg + (size_t)r * (NSEQ / 2) + c);
        }
        asm volatile("cp.async.commit_group;" ::: "memory");
    };

    // Prologue: K0,V0,K1 staged; QK(0) issued before the loop.
    stageK(0, 0);
    stageV(0, 0);
    stageK(1, 1);
    asm volatile("cp.async.wait_group 0;" ::: "memory");
    __syncthreads();

    float s[8][4];
    #pragma unroll
    for (int nt = 0; nt < 8; nt++)
        #pragma unroll
        for (int j = 0; j < 4; j++) s[nt][j] = -EOFF;
    {
        const unsigned* Ks = Kb;
        #pragma unroll
        for (int kc = 0; kc < 2; kc++)
            #pragma unroll
            for (int nt = 0; nt < 8; nt++) {
                uint2 kk = *(const uint2*)&Ks[(nt * 8 + g) * KPW + kc * 8 + 2 * t];
                mma16(s[nt], qa[kc][0], qa[kc][1], qa[kc][2], qa[kc][3], kk.x, kk.y);
            }
    }

    for (int kt = 0; kt < NT; kt++) {
        __syncthreads();
        if (kt + 2 < NT) stageK(kt & 1, kt + 2);
        if (kt + 1 < NT) stageV((kt + 1) & 1, kt + 1);
        if (kt + 2 < NT)      asm volatile("cp.async.wait_group 2;" ::: "memory");
        else if (kt + 1 < NT) asm volatile("cp.async.wait_group 1;" ::: "memory");
        else                  asm volatile("cp.async.wait_group 0;" ::: "memory");
        __syncthreads();

        // ---- mask (fp32 additive), then f16x2 cvt+exp2 -> packed P words
        uint2 mw0 = *(const uint2*)&mrow0[kt * 2];
        uint2 mw1 = *(const uint2*)&mrow1[kt * 2];
        #pragma unroll
        for (int nt = 0; nt < 8; nt++) {
            int sh = (nt * 8 + 2 * t) & 31;
            unsigned w0 = (nt < 4) ? mw0.x : mw0.y;
            unsigned w1 = (nt < 4) ? mw1.x : mw1.y;
            if (!((w0 >> sh) & 1))       s[nt][0] += NEGV;
            if (!((w0 >> (sh + 1)) & 1)) s[nt][1] += NEGV;
            if (!((w1 >> sh) & 1))       s[nt][2] += NEGV;
            if (!((w1 >> (sh + 1)) & 1)) s[nt][3] += NEGV;
        }
        unsigned pa[4][4];
        #pragma unroll
        for (int j = 0; j < 4; j++) {
            pa[j][0] = ex2_h2(cvt_h2(s[2*j][0],   s[2*j][1]));
            pa[j][1] = ex2_h2(cvt_h2(s[2*j][2],   s[2*j][3]));
            pa[j][2] = ex2_h2(cvt_h2(s[2*j+1][0], s[2*j+1][1]));
            pa[j][3] = ex2_h2(cvt_h2(s[2*j+1][2], s[2*j+1][3]));
        }
        #pragma unroll
        for (int nt = 0; nt < 8; nt++)
            #pragma unroll
            for (int j = 0; j < 4; j++) s[nt][j] = -EOFF;

        // ---- interleaved dual-stream mma: 20 PV (incl. l-block nt=4)
        //      woven with 16 QK(kt+1)
        const unsigned* Kn = Kb + ((kt + 1) & 1) * KT_W;
        const unsigned* Vc = Vb + (kt & 1) * VT_W;
        if (kt + 1 < NT) {
            int qi = 0;
            #pragma unroll
            for (int step = 0; step < 20; step++) {
                {
                    int j = step / 5, nt = step % 5;
                    uint2 vv = *(const uint2*)&Vc[(nt * 8 + g) * VPW + j * 8 + 2 * t];
                    mma16(o[nt], pa[j][0], pa[j][1], pa[j][2], pa[j][3], vv.x, vv.y);
                }
                if (step % 5 != 4) {
                    int kc = qi >> 3, nt = qi & 7; qi++;
                    uint2 kk = *(const uint2*)&Kn[(nt * 8 + g) * KPW + kc * 8 + 2 * t];
                    mma16(s[nt], qa[kc][0], qa[kc][1], qa[kc][2], qa[kc][3], kk.x, kk.y);
                }
            }
        } else {
            #pragma unroll
            for (int step = 0; step < 20; step++) {
                int j = step / 5, nt = step % 5;
                uint2 vv = *(const uint2*)&Vc[(nt * 8 + g) * VPW + j * 8 + 2 * t];
                mma16(o[nt], pa[j][0], pa[j][1], pa[j][2], pa[j][3], vv.x, vv.y);
            }
        }
    }

    // epilogue: l lives in o[4][0]/o[4][2] of the t==0 lane (col 32)
    float l0 = __shfl_sync(0xffffffffu, o[4][0], lane & ~3);
    float l1 = __shfl_sync(0xffffffffu, o[4][2], lane & ~3);
    float inv0 = 1.f / l0, inv1 = 1.f / l1;

    const int b = bh >> 2, h = bh & 3;
    float* d0 = g_attn + ((size_t)b * NSEQ + r0) * EDIM + h * DHEAD;
    float* d1 = g_attn + ((size_t)b * NSEQ + r1) * EDIM + h * DHEAD;
    #pragma unroll
    for (int nt = 0; nt < 4; nt++) {
        int c = nt * 8 + 2 * t;
        *(float2*)&d0[c] = make_float2(o[nt][0] * inv0, o[nt][1] * inv0);
        *(float2*)&d1[c] = make_float2(o[nt][2] * inv1, o[nt][3] * inv1);
    }
}

// --------------------------------------------------------------------------
// Kernel 3: output projection (tf32 mma), 256 thr, tile 128 x 64, pipelined.
// --------------------------------------------------------------------------
__global__ __launch_bounds__(256) void out_proj_kernel(
    const float* __restrict__ w, const float* __restrict__ bias,
    float* __restrict__ out)
{
    __shared__ unsigned Xs[128 * 36];
    __shared__ unsigned Ws[64 * 36];

    const int tid = threadIdx.x;
    const int wp = tid >> 5, lane = tid & 31;
    const int g = lane >> 2, t = lane & 3;
    const int m0 = blockIdx.y * 128, c0 = blockIdx.x * 64;

    float acc[8][4];
    #pragma unroll
    for (int nt = 0; nt < 8; nt++)
        #pragma unroll
        for (int j = 0; j < 4; j++) acc[nt][j] = 0.f;

    gemm_kloop_pipelined(Xs, Ws, g_attn, w, m0, c0, tid, wp, g, t, acc);

    const int mrow0 = m0 + wp * 16 + g;
    #pragma unroll
    for (int nt = 0; nt < 8; nt++) {
        int cg = c0 + nt * 8 + 2 * t;
        float b0v = bias[cg], b1v = bias[cg + 1];
        #pragma unroll
        for (int rr = 0; rr < 2; rr++) {
            int m = mrow0 + rr * 8;
            *(float2*)&out[(size_t)m * EDIM + cg] =
                make_float2(acc[nt][rr * 2 + 0] + b0v, acc[nt][rr * 2 + 1] + b1v);
        }
    }
}

// --------------------------------------------------------------------------
extern "C" void kernel_launch(void* const* d_in, const int* in_sizes, int n_in,
                              void* d_out, int out_size)
{
    const float* x   = (const float*)d_in[0];
    const int*   adj = (const int*)  d_in[1];
    const float* ipw = (const float*)d_in[2];
    const float* ipb = (const float*)d_in[3];
    const float* ow  = (const float*)d_in[4];
    const float* ob  = (const float*)d_in[5];
    float* out = (float*)d_out;

    (void)in_sizes; (void)n_in; (void)out_size;

    maskpack_kernel<<<16384, 256>>>(adj);
    qkv_proj_kernel<<<dim3(6, 128), 256>>>(x, ipw, ipb);
    attn_kernel<<<dim3(32, 32), 128>>>();
    out_proj_kernel<<<dim3(2, 128), 256>>>(ow, ob, out);
}

// round 17
// speedup vs baseline: 1.3384x; 1.0858x over previous
#include <cuda_runtime.h>
#include <cuda_fp16.h>
#include <cstdint>

#define BSZ   8
#define NSEQ  2048
#define EDIM  128
#define HEADS 4
#define DHEAD 32
#define NEGV  -1e9f
#define QS2    0.25503482120645087f          // (1/sqrt(32)) * log2(e)
#define EOFF   6.0f                          // fixed exponent offset (log2 domain)
#define NT     (NSEQ / 64)                   // 32 kv tiles

// Scratch. Q/K d-words and Vt kv-words are PERMUTED within 8-word groups
// (perm(x) = 2*(x&3) + (x>>2)) so mma B/A fragment pairs (t, t+4) are
// physically adjacent -> single LDS.64 / LDG.64.
__device__ unsigned g_qw[(size_t)BSZ * HEADS * NSEQ * (DHEAD / 2)];
__device__ unsigned g_kw[(size_t)BSZ * HEADS * NSEQ * (DHEAD / 2)];
__device__ __half   g_vt[(size_t)BSZ * HEADS * DHEAD * NSEQ];
__device__ float    g_attn[(size_t)BSZ * NSEQ * EDIM];
__device__ unsigned g_mask[(size_t)NSEQ * (NSEQ / 32)];

// --------------------------------------------------------------------------
__device__ __forceinline__ unsigned f2tf(float f) {
    unsigned r; asm("cvt.rna.tf32.f32 %0, %1;" : "=r"(r) : "f"(f)); return r;
}
__device__ __forceinline__ unsigned packh2(float a, float b) {
    __half2 h = __floats2half2_rn(a, b); return *(unsigned*)&h;
}
__device__ __forceinline__ unsigned cvt_h2(float a, float b) {
    unsigned r;
    asm("cvt.rn.f16x2.f32 %0, %1, %2;" : "=r"(r) : "f"(b), "f"(a));
    return r;
}
__device__ __forceinline__ unsigned ex2_h2(unsigned x) {
    unsigned r;
    asm("ex2.approx.f16x2 %0, %1;" : "=r"(r) : "r"(x));
    return r;
}
__device__ __forceinline__ void mma8(float* c,
                                     unsigned a0, unsigned a1, unsigned a2, unsigned a3,
                                     unsigned b0, unsigned b1) {
    asm volatile(
        "mma.sync.aligned.m16n8k8.row.col.f32.tf32.tf32.f32 "
        "{%0,%1,%2,%3}, {%4,%5,%6,%7}, {%8,%9}, {%0,%1,%2,%3};"
        : "+f"(c[0]), "+f"(c[1]), "+f"(c[2]), "+f"(c[3])
        : "r"(a0), "r"(a1), "r"(a2), "r"(a3), "r"(b0), "r"(b1));
}
__device__ __forceinline__ void mma16(float* c,
                                      unsigned a0, unsigned a1, unsigned a2, unsigned a3,
                                      unsigned b0, unsigned b1) {
    asm volatile(
        "mma.sync.aligned.m16n8k16.row.col.f32.f16.f16.f32 "
        "{%0,%1,%2,%3}, {%4,%5,%6,%7}, {%8,%9}, {%0,%1,%2,%3};"
        : "+f"(c[0]), "+f"(c[1]), "+f"(c[2]), "+f"(c[3])
        : "r"(a0), "r"(a1), "r"(a2), "r"(a3), "r"(b0), "r"(b1));
}
__device__ __forceinline__ void cpa16(void* dst, const void* src) {
    unsigned d = (unsigned)__cvta_generic_to_shared(dst);
    asm volatile("cp.async.ca.shared.global [%0], [%1], 16;" :: "r"(d), "l"(src));
}
__device__ __forceinline__ int permw(int x) { return 2 * (x & 3) + (x >> 2); }

// --------------------------------------------------------------------------
// Register-staged pipelined GEMM K-loop (shared by both projections):
// prefetch tile ko+1 into REGISTERS between the STS of tile ko and its mma
// stream -> the global-load latency overlaps the mma work.
// --------------------------------------------------------------------------
__device__ __forceinline__ void gemm_kloop_pipelined(
    unsigned* Xs, unsigned* Ws,
    const float* __restrict__ a_src, const float* __restrict__ b_src,
    int m0, int c0, int tid, int wp, int g, int t, float acc[8][4])
{
    float4 xr4[4];
    float4 wr4[2];

    #pragma unroll
    for (int u = 0; u < 4; u++) {
        int i = tid + u * 256;
        int r = i >> 3, c4 = (i & 7) * 4;
        xr4[u] = *(const float4*)&a_src[(size_t)(m0 + r) * EDIM + c4];
    }
    #pragma unroll
    for (int u = 0; u < 2; u++) {
        int i = tid + u * 256;
        int r = i >> 3, c4 = (i & 7) * 4;
        wr4[u] = *(const float4*)&b_src[(size_t)(c0 + r) * EDIM + c4];
    }

    #pragma unroll
    for (int ko = 0; ko < 4; ko++) {
        if (ko) __syncthreads();   // previous mma done reading smem

        #pragma unroll
        for (int u = 0; u < 4; u++) {
            int i = tid + u * 256;
            int r = i >> 3, c4 = (i & 7) * 4;
            *(uint4*)&Xs[r * 36 + c4] =
                make_uint4(f2tf(xr4[u].x), f2tf(xr4[u].y),
                           f2tf(xr4[u].z), f2tf(xr4[u].w));
        }
        #pragma unroll
        for (int u = 0; u < 2; u++) {
            int i = tid + u * 256;
            int r = i >> 3, c4 = (i & 7) * 4;
            *(uint4*)&Ws[r * 36 + c4] =
                make_uint4(f2tf(wr4[u].x), f2tf(wr4[u].y),
                           f2tf(wr4[u].z), f2tf(wr4[u].w));
        }

        if (ko < 3) {
            int kb = (ko + 1) * 32;
            #pragma unroll
            for (int u = 0; u < 4; u++) {
                int i = tid + u * 256;
                int r = i >> 3, c4 = (i & 7) * 4;
                xr4[u] = *(const float4*)&a_src[(size_t)(m0 + r) * EDIM + kb + c4];
            }
            #pragma unroll
            for (int u = 0; u < 2; u++) {
                int i = tid + u * 256;
                int r = i >> 3, c4 = (i & 7) * 4;
                wr4[u] = *(const float4*)&b_src[(size_t)(c0 + r) * EDIM + kb + c4];
            }
        }
        __syncthreads();

        #pragma unroll
        for (int kc = 0; kc < 4; kc++) {
            const unsigned* xr = &Xs[(wp * 16 + g) * 36 + kc * 8 + t];
            unsigned a0 = xr[0], a1 = xr[8 * 36], a2 = xr[4], a3 = xr[8 * 36 + 4];
            #pragma unroll
            for (int nt = 0; nt < 8; nt++) {
                unsigned b0 = Ws[(nt * 8 + g) * 36 + kc * 8 + t];
                unsigned b1 = Ws[(nt * 8 + g) * 36 + kc * 8 + t + 4];
                mma8(acc[nt], a0, a1, a2, a3, b0, b1);
            }
        }
    }
}

// --------------------------------------------------------------------------
// Kernel 1 (FUSED): blocks 0..767 = QKV projection (pipelined tf32 mma,
// tile 128x64); blocks 768..1791 = adj[0] bit-packing (8 warps x 16 ballot
// words each).  The DRAM-bound mask work fills scheduling gaps of the
// compute-bound qkv blocks instead of running as a serial prologue kernel.
// --------------------------------------------------------------------------
#define QKV_BLOCKS  768
#define MASK_BLOCKS 1024

__global__ __launch_bounds__(256) void qkv_mask_kernel(
    const float* __restrict__ x, const float* __restrict__ w,
    const float* __restrict__ bias, const int* __restrict__ adj)
{
    __shared__ unsigned Xs[128 * 36];
    __shared__ unsigned Ws[64 * 36];

    const int bid = blockIdx.x;
    const int tid = threadIdx.x;

    if (bid >= QKV_BLOCKS) {
        // ---- mask packing: 128 words per block
        const int mb   = bid - QKV_BLOCKS;
        const int wid  = tid >> 5, lane = tid & 31;
        const int wbase = mb * 128 + wid * 16;
        #pragma unroll
        for (int j = 0; j < 16; j++) {
            int w_ = wbase + j;
            int n = w_ >> 6, word = w_ & 63;
            int v = adj[(size_t)n * NSEQ + word * 32 + lane];
            unsigned m = __ballot_sync(0xffffffffu, v != 0);
            if (lane == 0) g_mask[w_] = m;
        }
        return;
    }

    const int wp = tid >> 5, lane = tid & 31;
    const int g = lane >> 2, t = lane & 3;
    const int m0 = (bid / 6) * 128, c0 = (bid % 6) * 64;

    float acc[8][4];
    #pragma unroll
    for (int nt = 0; nt < 8; nt++)
        #pragma unroll
        for (int j = 0; j < 4; j++) acc[nt][j] = 0.f;

    gemm_kloop_pipelined(Xs, Ws, x, w, m0, c0, tid, wp, g, t, acc);

    const int bb = m0 >> 11;
    const int n0 = m0 & (NSEQ - 1);
    const int mrow0 = m0 + wp * 16 + g;

    if (c0 < 256) {
        // ---- Q / K epilogue (permuted half2 words)
        #pragma unroll
        for (int nt = 0; nt < 8; nt++) {
            int cg = c0 + nt * 8 + 2 * t;
            float b0v = bias[cg], b1v = bias[cg + 1];
            int part = cg >> 7;
            int e = cg & 127, hh = e >> 5, d0 = e & 31;
            int wrd = d0 >> 1;
            int wperm = (wrd & ~7) | permw(wrd & 7);
            #pragma unroll
            for (int rr = 0; rr < 2; rr++) {
                int m = mrow0 + rr * 8;
                int bbm = m >> 11, n = m & (NSEQ - 1);
                int bh = bbm * HEADS + hh;
                float v0 = acc[nt][rr * 2 + 0] + b0v;
                float v1 = acc[nt][rr * 2 + 1] + b1v;
                if (part == 0) {
                    g_qw[((size_t)bh * NSEQ + n) * 16 + wperm] =
                        packh2(v0 * QS2, v1 * QS2);
                } else {
                    g_kw[((size_t)bh * NSEQ + n) * 16 + wperm] = packh2(v0, v1);
                }
            }
        }
    } else {
        // ---- V epilogue: stage [e][n] tile in smem, write coalesced
        __syncthreads();            // done reading Xs in mma loop
        __half* sT = (__half*)Xs;   // 64 x 136 halves = 17408 B (fits in Xs)
        #pragma unroll
        for (int nt = 0; nt < 8; nt++) {
            int cg = c0 + nt * 8 + 2 * t;
            float b0v = bias[cg], b1v = bias[cg + 1];
            int e0 = nt * 8 + 2 * t;   // block-local e (0..63)
            #pragma unroll
            for (int rr = 0; rr < 2; rr++) {
                int nl = wp * 16 + g + rr * 8;   // block-local n (0..127)
                sT[(e0)     * 136 + nl] = __float2half_rn(acc[nt][rr * 2 + 0] + b0v);
                sT[(e0 + 1) * 136 + nl] = __float2half_rn(acc[nt][rr * 2 + 1] + b1v);
            }
        }
        __syncthreads();

        const unsigned* sTw = (const unsigned*)sT;   // row stride 68 words
        const int ebase = c0 - 256;                  // 0 or 64
        #pragma unroll
        for (int r8 = 0; r8 < 8; r8++) {
            int row = wp * 8 + r8;                   // 0..63
            int e = ebase + row;
            int h = e >> 5, d0v = e & 31;
            size_t basev = ((size_t)(bb * HEADS + h) * DHEAD + d0v) * NSEQ + n0;
            #pragma unroll
            for (int wi = 0; wi < 2; wi++) {
                int pos = ((lane >> 3) << 3) | permw(lane & 7);  // permuted word
                unsigned word = sTw[row * 68 + wi * 32 + lane];
                *(unsigned*)&g_vt[basev + wi * 64 + pos * 2] = word;
            }
        }
    }
}

// --------------------------------------------------------------------------
// Kernel 2: flash attention — the proven 113.2us body VERBATIM.
// fp16 mma, pipelined QK(kt+1)/PV(kt), s init -EOFF, f16x2 cvt+ex2,
// l via helper ones-rows in Vt (PV mma accumulates it), LDS.64 fragments.
// 128 thr (4 warps), 64 q rows/block, 64 kv/iter, grid (32, 32).
// --------------------------------------------------------------------------
#define KPW 24                 // K smem pitch (16 data + 8 pad)
#define VPW 40                 // Vt smem pitch (32 data + 8 pad)
#define KT_W (64 * KPW)
#define VT_W (40 * VPW)        // rows 32..39 = ones/zeros helper

__global__ __launch_bounds__(128) void attn_kernel()
{
    __shared__ unsigned Kb[2 * KT_W];
    __shared__ unsigned Vb[2 * VT_W];

    const int tid = threadIdx.x;
    const int wp = tid >> 5, lane = tid & 31;
    const int g = lane >> 2, t = lane & 3;
    const int qt = blockIdx.x, bh = blockIdx.y;

    const int r0 = qt * 64 + wp * 16 + g;
    const int r1 = r0 + 8;

    // helper rows (32..39) in both V buffers: row 32 = 1.0h pairs, rest 0
    #pragma unroll
    for (int i = tid; i < 2 * 8 * 32; i += 128) {
        int buf = i >> 8, rem = i & 255;
        int r = rem >> 5, c = rem & 31;
        Vb[buf * VT_W + (32 + r) * VPW + c] = (r == 0) ? 0x3C003C00u : 0u;
    }

    // Q fragments: permuted words -> one uint2 per (kc, row)
    unsigned qa[2][4];
    {
        const unsigned* q0 = g_qw + ((size_t)bh * NSEQ + r0) * 16;
        const unsigned* q1 = g_qw + ((size_t)bh * NSEQ + r1) * 16;
        #pragma unroll
        for (int kc = 0; kc < 2; kc++) {
            uint2 lo = *(const uint2*)&q0[kc * 8 + 2 * t];
            uint2 hi = *(const uint2*)&q1[kc * 8 + 2 * t];
            qa[kc][0] = lo.x; qa[kc][1] = hi.x;
            qa[kc][2] = lo.y; qa[kc][3] = hi.y;
        }
    }

    float o[5][4];
    #pragma unroll
    for (int nt = 0; nt < 5; nt++)
        #pragma unroll
        for (int j = 0; j < 4; j++) o[nt][j] = 0.f;

    const unsigned* mrow0 = &g_mask[(size_t)r0 * 64];
    const unsigned* mrow1 = &g_mask[(size_t)r1 * 64];
    const unsigned* kbase = g_kw + (size_t)bh * NSEQ * 16;
    const unsigned* vbase = (const unsigned*)g_vt + (size_t)bh * DHEAD * (NSEQ / 2);

    auto stageK = [&](int buf, int ktile) {
        const unsigned* kg = kbase + (size_t)ktile * 64 * 16;
        unsigned* kd = Kb + buf * KT_W;
        #pragma unroll
        for (int i = tid; i < 256; i += 128) {
            int r = i >> 2, c = (i & 3) * 4;
            cpa16(&kd[r * KPW + c], kg + r * 16 + c);
        }
        asm volatile("cp.async.commit_group;" ::: "memory");
    };
    auto stageV = [&](int buf, int ktile) {
        const unsigned* vg = vbase + (size_t)ktile * 32;
        unsigned* vd = Vb + buf * VT_W;
        #pragma unroll
        for (int i = tid; i < 256; i += 128) {
            int r = i >> 3, c = (i & 7) * 4;
            cpa16(&vd[r * VPW + c], vg + (size_t)r * (NSEQ / 2) + c);
        }
        asm volatile("cp.async.commit_group;" ::: "memory");
    };

    // Prologue: K0,V0,K1 staged; QK(0) issued before the loop.
    stageK(0, 0);
    stageV(0, 0);
    stageK(1, 1);
    asm volatile("cp.async.wait_group 0;" ::: "memory");
    __syncthreads();

    float s[8][4];
    #pragma unroll
    for (int nt = 0; nt < 8; nt++)
        #pragma unroll
        for (int j = 0; j < 4; j++) s[nt][j] = -EOFF;
    {
        const unsigned* Ks = Kb;
        #pragma unroll
        for (int kc = 0; kc < 2; kc++)
            #pragma unroll
            for (int nt = 0; nt < 8; nt++) {
                uint2 kk = *(const uint2*)&Ks[(nt * 8 + g) * KPW + kc * 8 + 2 * t];
                mma16(s[nt], qa[kc][0], qa[kc][1], qa[kc][2], qa[kc][3], kk.x, kk.y);
            }
    }

    for (int kt = 0; kt < NT; kt++) {
        __syncthreads();
        if (kt + 2 < NT) stageK(kt & 1, kt + 2);
        if (kt + 1 < NT) stageV((kt + 1) & 1, kt + 1);
        if (kt + 2 < NT)      asm volatile("cp.async.wait_group 2;" ::: "memory");
        else if (kt + 1 < NT) asm volatile("cp.async.wait_group 1;" ::: "memory");
        else                  asm volatile("cp.async.wait_group 0;" ::: "memory");
        __syncthreads();

        // ---- mask (fp32 additive), then f16x2 cvt+exp2 -> packed P words
        uint2 mw0 = *(const uint2*)&mrow0[kt * 2];
        uint2 mw1 = *(const uint2*)&mrow1[kt * 2];
        #pragma unroll
        for (int nt = 0; nt < 8; nt++) {
            int sh = (nt * 8 + 2 * t) & 31;
            unsigned w0 = (nt < 4) ? mw0.x : mw0.y;
            unsigned w1 = (nt < 4) ? mw1.x : mw1.y;
            if (!((w0 >> sh) & 1))       s[nt][0] += NEGV;
            if (!((w0 >> (sh + 1)) & 1)) s[nt][1] += NEGV;
            if (!((w1 >> sh) & 1))       s[nt][2] += NEGV;
            if (!((w1 >> (sh + 1)) & 1)) s[nt][3] += NEGV;
        }
        unsigned pa[4][4];
        #pragma unroll
        for (int j = 0; j < 4; j++) {
            pa[j][0] = ex2_h2(cvt_h2(s[2*j][0],   s[2*j][1]));
            pa[j][1] = ex2_h2(cvt_h2(s[2*j][2],   s[2*j][3]));
            pa[j][2] = ex2_h2(cvt_h2(s[2*j+1][0], s[2*j+1][1]));
            pa[j][3] = ex2_h2(cvt_h2(s[2*j+1][2], s[2*j+1][3]));
        }
        #pragma unroll
        for (int nt = 0; nt < 8; nt++)
            #pragma unroll
            for (int j = 0; j < 4; j++) s[nt][j] = -EOFF;

        // ---- interleaved dual-stream mma: 20 PV (incl. l-block nt=4)
        //      woven with 16 QK(kt+1)
        const unsigned* Kn = Kb + ((kt + 1) & 1) * KT_W;
        const unsigned* Vc = Vb + (kt & 1) * VT_W;
        if (kt + 1 < NT) {
            int qi = 0;
            #pragma unroll
            for (int step = 0; step < 20; step++) {
                {
                    int j = step / 5, nt = step % 5;
                    uint2 vv = *(const uint2*)&Vc[(nt * 8 + g) * VPW + j * 8 + 2 * t];
                    mma16(o[nt], pa[j][0], pa[j][1], pa[j][2], pa[j][3], vv.x, vv.y);
                }
                if (step % 5 != 4) {
                    int kc = qi >> 3, nt = qi & 7; qi++;
                    uint2 kk = *(const uint2*)&Kn[(nt * 8 + g) * KPW + kc * 8 + 2 * t];
                    mma16(s[nt], qa[kc][0], qa[kc][1], qa[kc][2], qa[kc][3], kk.x, kk.y);
                }
            }
        } else {
            #pragma unroll
            for (int step = 0; step < 20; step++) {
                int j = step / 5, nt = step % 5;
                uint2 vv = *(const uint2*)&Vc[(nt * 8 + g) * VPW + j * 8 + 2 * t];
                mma16(o[nt], pa[j][0], pa[j][1], pa[j][2], pa[j][3], vv.x, vv.y);
            }
        }
    }

    // epilogue: l lives in o[4][0]/o[4][2] of the t==0 lane (col 32)
    float l0 = __shfl_sync(0xffffffffu, o[4][0], lane & ~3);
    float l1 = __shfl_sync(0xffffffffu, o[4][2], lane & ~3);
    float inv0 = 1.f / l0, inv1 = 1.f / l1;

    const int b = bh >> 2, h = bh & 3;
    float* d0 = g_attn + ((size_t)b * NSEQ + r0) * EDIM + h * DHEAD;
    float* d1 = g_attn + ((size_t)b * NSEQ + r1) * EDIM + h * DHEAD;
    #pragma unroll
    for (int nt = 0; nt < 4; nt++) {
        int c = nt * 8 + 2 * t;
        *(float2*)&d0[c] = make_float2(o[nt][0] * inv0, o[nt][1] * inv0);
        *(float2*)&d1[c] = make_float2(o[nt][2] * inv1, o[nt][3] * inv1);
    }
}

// --------------------------------------------------------------------------
// Kernel 3: output projection (tf32 mma), 256 thr, tile 128 x 64, pipelined.
// --------------------------------------------------------------------------
__global__ __launch_bounds__(256) void out_proj_kernel(
    const float* __restrict__ w, const float* __restrict__ bias,
    float* __restrict__ out)
{
    __shared__ unsigned Xs[128 * 36];
    __shared__ unsigned Ws[64 * 36];

    const int tid = threadIdx.x;
    const int wp = tid >> 5, lane = tid & 31;
    const int g = lane >> 2, t = lane & 3;
    const int m0 = blockIdx.y * 128, c0 = blockIdx.x * 64;

    float acc[8][4];
    #pragma unroll
    for (int nt = 0; nt < 8; nt++)
        #pragma unroll
        for (int j = 0; j < 4; j++) acc[nt][j] = 0.f;

    gemm_kloop_pipelined(Xs, Ws, g_attn, w, m0, c0, tid, wp, g, t, acc);

    const int mrow0 = m0 + wp * 16 + g;
    #pragma unroll
    for (int nt = 0; nt < 8; nt++) {
        int cg = c0 + nt * 8 + 2 * t;
        float b0v = bias[cg], b1v = bias[cg + 1];
        #pragma unroll
        for (int rr = 0; rr < 2; rr++) {
            int m = mrow0 + rr * 8;
            *(float2*)&out[(size_t)m * EDIM + cg] =
                make_float2(acc[nt][rr * 2 + 0] + b0v, acc[nt][rr * 2 + 1] + b1v);
        }
    }
}

// --------------------------------------------------------------------------
extern "C" void kernel_launch(void* const* d_in, const int* in_sizes, int n_in,
                              void* d_out, int out_size)
{
    const float* x   = (const float*)d_in[0];
    const int*   adj = (const int*)  d_in[1];
    const float* ipw = (const float*)d_in[2];
    const float* ipb = (const float*)d_in[3];
    const float* ow  = (const float*)d_in[4];
    const float* ob  = (const float*)d_in[5];
    float* out = (float*)d_out;

    (void)in_sizes; (void)n_in; (void)out_size;

    qkv_mask_kernel<<<QKV_BLOCKS + MASK_BLOCKS, 256>>>(x, ipw, ipb, adj);
    attn_kernel<<<dim3(32, 32), 128>>>();
    out_proj_kernel<<<dim3(2, 128), 256>>>(ow, ob, out);
}